// round 7
// baseline (speedup 1.0000x reference)
#include <cuda_runtime.h>

// DeepFilter, 2 time-steps per thread (shared tap rows).
// spec:  (B=8, 2, T=4096, F=481) f32
// coefs: (B=8, 10, T=4096, 256) f32  (c[0..4]=real taps, c[5..9]=imag taps)

#define NUM_FREQS 256
#define FRAME_SIZE 5
#define T_DIM 4096
#define F_TOTAL 481
#define B_DIM 8
#define NPASS (F_TOTAL - NUM_FREQS)   // 225

__global__ __launch_bounds__(128, 10)
void deepfilter_kernel(const float* __restrict__ spec,
                       const float* __restrict__ coefs,
                       float* __restrict__ out)
{
    const int tid = threadIdx.x;
    const int t0 = blockIdx.x * 2;          // this block does t0 and t0+1
    const int b  = blockIdx.y;

    const long spec_ch = (long)T_DIM * F_TOTAL;
    const long spec_b  = 2 * spec_ch;
    const long coef_c  = (long)T_DIM * NUM_FREQS;
    const long coef_b  = 2 * FRAME_SIZE * coef_c;

    const float* sp = spec + (long)b * spec_b;
    float*       op = out  + (long)b * spec_b;

    if (tid < 64) {
        const int f0 = tid * 4;
        const float* cf0 = coefs + (long)b * coef_b + (long)t0 * NUM_FREQS + f0;
        const float* cf1 = cf0 + NUM_FREQS;

        float ar0[4] = {0,0,0,0}, ai0[4] = {0,0,0,0};
        float ar1[4] = {0,0,0,0}, ai1[4] = {0,0,0,0};

        #pragma unroll
        for (int j = 0; j < FRAME_SIZE + 1; j++) {       // 6 tap rows
            const int ts = t0 - (FRAME_SIZE - 1) + j;
            if (ts >= 0) {
                const float* srp = sp + (long)ts * F_TOTAL + f0;
                const float* sip = srp + spec_ch;
                float sr[4], si[4];
                #pragma unroll
                for (int u = 0; u < 4; u++) {
                    sr[u] = __ldg(srp + u);
                    si[u] = __ldg(sip + u);
                }

                if (j < FRAME_SIZE) {                    // tap k=j for output t0
                    const float4 cr = __ldcs((const float4*)(cf0 + (long)j * coef_c));
                    const float4 ci = __ldcs((const float4*)(cf0 + (long)(FRAME_SIZE + j) * coef_c));
                    const float crv[4] = {cr.x, cr.y, cr.z, cr.w};
                    const float civ[4] = {ci.x, ci.y, ci.z, ci.w};
                    #pragma unroll
                    for (int u = 0; u < 4; u++) {
                        ar0[u] = fmaf(sr[u], crv[u], fmaf(-si[u], civ[u], ar0[u]));
                        ai0[u] = fmaf(si[u], crv[u], fmaf(sr[u], civ[u], ai0[u]));
                    }
                }
                if (j >= 1) {                            // tap k=j-1 for output t0+1
                    const int k = j - 1;
                    const float4 cr = __ldcs((const float4*)(cf1 + (long)k * coef_c));
                    const float4 ci = __ldcs((const float4*)(cf1 + (long)(FRAME_SIZE + k) * coef_c));
                    const float crv[4] = {cr.x, cr.y, cr.z, cr.w};
                    const float civ[4] = {ci.x, ci.y, ci.z, ci.w};
                    #pragma unroll
                    for (int u = 0; u < 4; u++) {
                        ar1[u] = fmaf(sr[u], crv[u], fmaf(-si[u], civ[u], ar1[u]));
                        ai1[u] = fmaf(si[u], crv[u], fmaf(sr[u], civ[u], ai1[u]));
                    }
                }
            }
        }

        float* o0r = op + (long)t0 * F_TOTAL + f0;
        float* o0i = o0r + spec_ch;
        float* o1r = o0r + F_TOTAL;
        float* o1i = o0i + F_TOTAL;
        #pragma unroll
        for (int u = 0; u < 4; u++) {
            __stcs(o0r + u, ar0[u]);
            __stcs(o0i + u, ai0[u]);
            __stcs(o1r + u, ar1[u]);
            __stcs(o1i + u, ai1[u]);
        }
    } else {
        // Passthrough: bins 256..480 for t0 and t0+1, both channels.
        const int lid = tid - 64;
        const int total = 2 * 2 * NPASS;    // 900
        for (int i = lid; i < total; i += 64) {
            const int f    = i % NPASS;
            const int rest = i / NPASS;
            const int ch   = rest & 1;
            const int tt   = rest >> 1;
            const long off = (long)ch * spec_ch + (long)(t0 + tt) * F_TOTAL
                           + NUM_FREQS + f;
            __stcs(op + off, __ldg(sp + off));
        }
    }
}

extern "C" void kernel_launch(void* const* d_in, const int* in_sizes, int n_in,
                              void* d_out, int out_size)
{
    const float* spec  = (const float*)d_in[0];
    const float* coefs = (const float*)d_in[1];
    float* out = (float*)d_out;

    dim3 grid(T_DIM / 2, B_DIM);
    deepfilter_kernel<<<grid, 128>>>(spec, coefs, out);
}

// round 8
// speedup vs baseline: 1.1483x; 1.1483x over previous
#include <cuda_runtime.h>

// DeepFilter, branch-free main kernel (t>=4) + tiny boundary kernel (t<4).
// spec:  (B=8, 2, T=4096, F=481) f32
// coefs: (B=8, 10, T=4096, 256) f32  (c[0..4]=real taps, c[5..9]=imag taps)

#define NUM_FREQS 256
#define FRAME_SIZE 5
#define T_DIM 4096
#define F_TOTAL 481
#define B_DIM 8
#define NPASS (F_TOTAL - NUM_FREQS)   // 225

__global__ __launch_bounds__(128, 8)
void deepfilter_main(const float* __restrict__ spec,
                     const float* __restrict__ coefs,
                     float* __restrict__ out)
{
    const int tid = threadIdx.x;
    const int t   = blockIdx.x + (FRAME_SIZE - 1);   // t = 4 .. 4095
    const int b   = blockIdx.y;

    const long spec_ch = (long)T_DIM * F_TOTAL;
    const long spec_b  = 2 * spec_ch;
    const long coef_c  = (long)T_DIM * NUM_FREQS;
    const long coef_b  = 2 * FRAME_SIZE * coef_c;

    const float* sp_base = spec + (long)b * spec_b + (long)t * F_TOTAL;
    float*       ot_base = out  + (long)b * spec_b + (long)t * F_TOTAL;

    if (tid < 64) {
        const int f0 = tid * 4;
        const float* cf = coefs + (long)b * coef_b + (long)t * NUM_FREQS + f0;

        float ar0 = 0.f, ar1 = 0.f, ar2 = 0.f, ar3 = 0.f;
        float ai0 = 0.f, ai1 = 0.f, ai2 = 0.f, ai3 = 0.f;

        // Branch-free, fully unrolled: all loads hoistable into one batch.
        #pragma unroll
        for (int k = 0; k < FRAME_SIZE; k++) {
            const float4 cr = __ldcs((const float4*)(cf + (long)k * coef_c));
            const float4 ci = __ldcs((const float4*)(cf + (long)(FRAME_SIZE + k) * coef_c));

            const float* sr = sp_base + (long)(k - (FRAME_SIZE - 1)) * F_TOTAL + f0;
            const float* si = sr + spec_ch;

            const float sr0 = __ldg(sr + 0), sr1 = __ldg(sr + 1);
            const float sr2 = __ldg(sr + 2), sr3 = __ldg(sr + 3);
            const float si0 = __ldg(si + 0), si1 = __ldg(si + 1);
            const float si2 = __ldg(si + 2), si3 = __ldg(si + 3);

            ar0 = fmaf(sr0, cr.x, fmaf(-si0, ci.x, ar0));
            ar1 = fmaf(sr1, cr.y, fmaf(-si1, ci.y, ar1));
            ar2 = fmaf(sr2, cr.z, fmaf(-si2, ci.z, ar2));
            ar3 = fmaf(sr3, cr.w, fmaf(-si3, ci.w, ar3));

            ai0 = fmaf(si0, cr.x, fmaf(sr0, ci.x, ai0));
            ai1 = fmaf(si1, cr.y, fmaf(sr1, ci.y, ai1));
            ai2 = fmaf(si2, cr.z, fmaf(sr2, ci.z, ai2));
            ai3 = fmaf(si3, cr.w, fmaf(sr3, ci.w, ai3));
        }

        float* outr = ot_base + f0;
        float* outi = outr + spec_ch;
        __stcs(outr + 0, ar0); __stcs(outr + 1, ar1);
        __stcs(outr + 2, ar2); __stcs(outr + 3, ar3);
        __stcs(outi + 0, ai0); __stcs(outi + 1, ai1);
        __stcs(outi + 2, ai2); __stcs(outi + 3, ai3);
    } else {
        // Passthrough: bins 256..480, both channels (450 elems over 64 threads).
        const int lid = tid - 64;
        #pragma unroll
        for (int i = lid; i < 2 * NPASS; i += 64) {
            const int ch = (i >= NPASS);
            const int f  = NUM_FREQS + (ch ? i - NPASS : i);
            const long off = (long)ch * spec_ch + f;
            __stcs(ot_base + off, __ldg(sp_base + off));
        }
    }
}

// Boundary kernel: t = 0..3 (with zero-padded history) + their passthrough.
__global__ __launch_bounds__(128, 8)
void deepfilter_boundary(const float* __restrict__ spec,
                         const float* __restrict__ coefs,
                         float* __restrict__ out)
{
    const int tid = threadIdx.x;
    const int t   = blockIdx.x;          // 0..3
    const int b   = blockIdx.y;

    const long spec_ch = (long)T_DIM * F_TOTAL;
    const long spec_b  = 2 * spec_ch;
    const long coef_c  = (long)T_DIM * NUM_FREQS;
    const long coef_b  = 2 * FRAME_SIZE * coef_c;

    const float* sp_base = spec + (long)b * spec_b + (long)t * F_TOTAL;
    float*       ot_base = out  + (long)b * spec_b + (long)t * F_TOTAL;

    if (tid < 64) {
        const int f0 = tid * 4;
        const float* cf = coefs + (long)b * coef_b + (long)t * NUM_FREQS + f0;

        float ar[4] = {0,0,0,0}, ai[4] = {0,0,0,0};

        #pragma unroll
        for (int k = 0; k < FRAME_SIZE; k++) {
            const int ts = t + k - (FRAME_SIZE - 1);
            if (ts >= 0) {
                const float4 cr = *(const float4*)(cf + (long)k * coef_c);
                const float4 ci = *(const float4*)(cf + (long)(FRAME_SIZE + k) * coef_c);
                const float crv[4] = {cr.x, cr.y, cr.z, cr.w};
                const float civ[4] = {ci.x, ci.y, ci.z, ci.w};
                const float* sr = sp_base + (long)(ts - t) * F_TOTAL + f0;
                const float* si = sr + spec_ch;
                #pragma unroll
                for (int u = 0; u < 4; u++) {
                    const float s_r = sr[u], s_i = si[u];
                    ar[u] = fmaf(s_r, crv[u], fmaf(-s_i, civ[u], ar[u]));
                    ai[u] = fmaf(s_i, crv[u], fmaf(s_r, civ[u], ai[u]));
                }
            }
        }

        float* outr = ot_base + f0;
        float* outi = outr + spec_ch;
        #pragma unroll
        for (int u = 0; u < 4; u++) {
            outr[u] = ar[u];
            outi[u] = ai[u];
        }
    } else {
        const int lid = tid - 64;
        for (int i = lid; i < 2 * NPASS; i += 64) {
            const int ch = (i >= NPASS);
            const int f  = NUM_FREQS + (ch ? i - NPASS : i);
            const long off = (long)ch * spec_ch + f;
            ot_base[off] = sp_base[off];
        }
    }
}

extern "C" void kernel_launch(void* const* d_in, const int* in_sizes, int n_in,
                              void* d_out, int out_size)
{
    const float* spec  = (const float*)d_in[0];
    const float* coefs = (const float*)d_in[1];
    float* out = (float*)d_out;

    dim3 gridM(T_DIM - (FRAME_SIZE - 1), B_DIM);
    deepfilter_main<<<gridM, 128>>>(spec, coefs, out);

    dim3 gridB(FRAME_SIZE - 1, B_DIM);
    deepfilter_boundary<<<gridB, 128>>>(spec, coefs, out);
}

// round 10
// speedup vs baseline: 1.2513x; 1.0897x over previous
#include <cuda_runtime.h>

// DeepFilter, single kernel: branch-free bulk path (t>=4), guarded path (t<4).
// spec:  (B=8, 2, T=4096, F=481) f32
// coefs: (B=8, 10, T=4096, 256) f32  (c[0..4]=real taps, c[5..9]=imag taps)

#define NUM_FREQS 256
#define FRAME_SIZE 5
#define T_DIM 4096
#define F_TOTAL 481
#define B_DIM 8
#define NPASS (F_TOTAL - NUM_FREQS)   // 225

__global__ __launch_bounds__(128, 8)
void deepfilter_kernel(const float* __restrict__ spec,
                       const float* __restrict__ coefs,
                       float* __restrict__ out)
{
    const int tid = threadIdx.x;
    const int t   = blockIdx.x;
    const int b   = blockIdx.y;

    const long spec_ch = (long)T_DIM * F_TOTAL;
    const long spec_b  = 2 * spec_ch;
    const long coef_c  = (long)T_DIM * NUM_FREQS;
    const long coef_b  = 2 * FRAME_SIZE * coef_c;

    const float* sp_base = spec + (long)b * spec_b + (long)t * F_TOTAL;
    float*       ot_base = out  + (long)b * spec_b + (long)t * F_TOTAL;

    if (tid < 64) {
        const int f0 = tid * 4;
        const float* cf = coefs + (long)b * coef_b + (long)t * NUM_FREQS + f0;

        float ar0 = 0.f, ar1 = 0.f, ar2 = 0.f, ar3 = 0.f;
        float ai0 = 0.f, ai1 = 0.f, ai2 = 0.f, ai3 = 0.f;

        if (t >= FRAME_SIZE - 1) {
            // Bulk path: branch-free, fully unrolled — one big load batch.
            #pragma unroll
            for (int k = 0; k < FRAME_SIZE; k++) {
                const float4 cr = __ldcs((const float4*)(cf + (long)k * coef_c));
                const float4 ci = __ldcs((const float4*)(cf + (long)(FRAME_SIZE + k) * coef_c));

                const float* sr = sp_base + (long)(k - (FRAME_SIZE - 1)) * F_TOTAL + f0;
                const float* si = sr + spec_ch;

                const float sr0 = __ldg(sr + 0), sr1 = __ldg(sr + 1);
                const float sr2 = __ldg(sr + 2), sr3 = __ldg(sr + 3);
                const float si0 = __ldg(si + 0), si1 = __ldg(si + 1);
                const float si2 = __ldg(si + 2), si3 = __ldg(si + 3);

                ar0 = fmaf(sr0, cr.x, fmaf(-si0, ci.x, ar0));
                ar1 = fmaf(sr1, cr.y, fmaf(-si1, ci.y, ar1));
                ar2 = fmaf(sr2, cr.z, fmaf(-si2, ci.z, ar2));
                ar3 = fmaf(sr3, cr.w, fmaf(-si3, ci.w, ar3));

                ai0 = fmaf(si0, cr.x, fmaf(sr0, ci.x, ai0));
                ai1 = fmaf(si1, cr.y, fmaf(sr1, ci.y, ai1));
                ai2 = fmaf(si2, cr.z, fmaf(sr2, ci.z, ai2));
                ai3 = fmaf(si3, cr.w, fmaf(sr3, ci.w, ai3));
            }
        } else {
            // Boundary path: t = 0..3, zero-padded history.
            #pragma unroll
            for (int k = 0; k < FRAME_SIZE; k++) {
                const int ts = t + k - (FRAME_SIZE - 1);
                if (ts >= 0) {
                    const float4 cr = *(const float4*)(cf + (long)k * coef_c);
                    const float4 ci = *(const float4*)(cf + (long)(FRAME_SIZE + k) * coef_c);

                    const float* sr = sp_base + (long)(ts - t) * F_TOTAL + f0;
                    const float* si = sr + spec_ch;

                    const float sr0 = sr[0], sr1 = sr[1], sr2 = sr[2], sr3 = sr[3];
                    const float si0 = si[0], si1 = si[1], si2 = si[2], si3 = si[3];

                    ar0 = fmaf(sr0, cr.x, fmaf(-si0, ci.x, ar0));
                    ar1 = fmaf(sr1, cr.y, fmaf(-si1, ci.y, ar1));
                    ar2 = fmaf(sr2, cr.z, fmaf(-si2, ci.z, ar2));
                    ar3 = fmaf(sr3, cr.w, fmaf(-si3, ci.w, ar3));

                    ai0 = fmaf(si0, cr.x, fmaf(sr0, ci.x, ai0));
                    ai1 = fmaf(si1, cr.y, fmaf(sr1, ci.y, ai1));
                    ai2 = fmaf(si2, cr.z, fmaf(sr2, ci.z, ai2));
                    ai3 = fmaf(si3, cr.w, fmaf(sr3, ci.w, ai3));
                }
            }
        }

        float* outr = ot_base + f0;
        float* outi = outr + spec_ch;
        __stcs(outr + 0, ar0); __stcs(outr + 1, ar1);
        __stcs(outr + 2, ar2); __stcs(outr + 3, ar3);
        __stcs(outi + 0, ai0); __stcs(outi + 1, ai1);
        __stcs(outi + 2, ai2); __stcs(outi + 3, ai3);
    } else {
        // Passthrough: bins 256..480, both channels (450 elems over 64 threads).
        const int lid = tid - 64;
        #pragma unroll
        for (int i = lid; i < 2 * NPASS; i += 64) {
            const int ch = (i >= NPASS);
            const int f  = NUM_FREQS + (ch ? i - NPASS : i);
            const long off = (long)ch * spec_ch + f;
            __stcs(ot_base + off, __ldg(sp_base + off));
        }
    }
}

extern "C" void kernel_launch(void* const* d_in, const int* in_sizes, int n_in,
                              void* d_out, int out_size)
{
    const float* spec  = (const float*)d_in[0];
    const float* coefs = (const float*)d_in[1];
    float* out = (float*)d_out;

    dim3 grid(T_DIM, B_DIM);
    deepfilter_kernel<<<grid, 128>>>(spec, coefs, out);
}